// round 5
// baseline (speedup 1.0000x reference)
#include <cuda_runtime.h>
#include <math.h>
#include <stdint.h>

#define BB 16
#define TT 600
#define VV 20000
#define EE 300
#define HH 512
#define BT (BB*TT)   // 9600

// ---------------- scratch ----------------
__device__ float g_P[(size_t)BT*1024];   // [9600][1024]: 0..511 = enc@aw2g, 512..1023 = enc@aw2c
__device__ float g_z1[BB*2048];
__device__ float g_z2[BB*2048];
__device__ float g_q[BB*1024];
__device__ float g_ha[BB*HH];
__device__ float g_sg[BB*TT];
__device__ float g_sc[BB*TT];
__device__ float g_aligng[BB*TT];
__device__ float g_alignc[BB*TT];
__device__ float g_ctx[BB*HH];
__device__ float g_logits[(size_t)BB*VV];
__device__ float g_vred[BB*2];
__device__ float g_switch[BB];

__device__ __forceinline__ float sigf(float x){ return 1.0f/(1.0f+expf(-x)); }

// ---------------- init: write biases / zeros into accumulators ----------------
__global__ void init_kernel(const float* __restrict__ b1, const float* __restrict__ b2,
                            const float* __restrict__ bh) {
  int idx = blockIdx.x*blockDim.x + threadIdx.x;
  // layout: [0,32768) z1 | [32768,65536) z2 | [65536,81920) q | [81920,90112) ha | [90112,98304) ctx
  if (idx < 32768)            g_z1[idx] = b1[idx & 2047];
  else if (idx < 65536)       g_z2[idx-32768] = b2[idx & 2047];
  else if (idx < 81920)       g_q[idx-65536] = 0.f;
  else if (idx < 90112)       g_ha[idx-81920] = bh[idx & 511];
  else if (idx < 98304)       g_ctx[idx-90112] = 0.f;
}

// ---------------- big SGEMM: g_P[9600,1024] = enc_outs[9600,512] @ [aw2g | aw2c] ----------------
// 128x128 tile, 256 threads, 8x8 per thread
__global__ void sgemm_attn_kernel(const float* __restrict__ A,
                                  const float* __restrict__ Wg,
                                  const float* __restrict__ Wc) {
  __shared__ __align__(16) float As[16][132];
  __shared__ __align__(16) float Bs[16][128];
  int tid = threadIdx.x;                 // 256
  int bm = blockIdx.x * 128;             // 75
  int bn = blockIdx.y * 128;             // 8
  const float* W = (bn < 512) ? Wg : Wc;
  int wc0 = bn & 511;
  int tm = tid >> 4, tn = tid & 15;
  float acc[8][8];
  #pragma unroll
  for (int i=0;i<8;i++)
    #pragma unroll
    for (int j=0;j<8;j++) acc[i][j]=0.f;

  for (int kc=0; kc<512; kc+=16) {
    #pragma unroll
    for (int i=0;i<2;i++){
      int f = tid*2 + i;                  // 0..511 float4s of A-chunk
      int row = f >> 2;
      int kq  = (f & 3) << 2;
      float4 av = *(const float4*)&A[(size_t)(bm+row)*512 + kc + kq];
      As[kq+0][row]=av.x; As[kq+1][row]=av.y; As[kq+2][row]=av.z; As[kq+3][row]=av.w;
    }
    #pragma unroll
    for (int i=0;i<2;i++){
      int f = tid*2 + i;                  // 0..511 float4s of B-chunk
      int kb = f >> 5;
      int c4 = (f & 31) << 2;
      *(float4*)&Bs[kb][c4] = *(const float4*)&W[(size_t)(kc+kb)*512 + wc0 + c4];
    }
    __syncthreads();
    #pragma unroll
    for (int k=0;k<16;k++){
      float4 a0 = *(const float4*)&As[k][tm*8];
      float4 a1 = *(const float4*)&As[k][tm*8+4];
      float4 b0 = *(const float4*)&Bs[k][tn*8];
      float4 b1 = *(const float4*)&Bs[k][tn*8+4];
      float am[8] = {a0.x,a0.y,a0.z,a0.w,a1.x,a1.y,a1.z,a1.w};
      float bv[8] = {b0.x,b0.y,b0.z,b0.w,b1.x,b1.y,b1.z,b1.w};
      #pragma unroll
      for (int i=0;i<8;i++)
        #pragma unroll
        for (int j=0;j<8;j++)
          acc[i][j] = fmaf(am[i], bv[j], acc[i][j]);
    }
    __syncthreads();
  }
  #pragma unroll
  for (int i=0;i<8;i++){
    float* orow = &g_P[(size_t)(bm + tm*8 + i)*1024 + bn + tn*8];
    *(float4*)&orow[0] = make_float4(acc[i][0],acc[i][1],acc[i][2],acc[i][3]);
    *(float4*)&orow[4] = make_float4(acc[i][4],acc[i][5],acc[i][6],acc[i][7]);
  }
}

// ---------------- small-M GEMM, K-split + atomic accumulate ----------------
struct GArgs {
  const float* A0; const float* A1;
  const float* W0; const float* W1;
  const int* xidx; const float* emb;
  float* C;
  int K; int N;
};

enum { V_Z1=0, V_Z2=1, V_Q=2, V_HA=3 };

template<int VAR>
__device__ __forceinline__ float loadA(const GArgs& g, int b, int k) {
  if (VAR==V_Z1) {
    if (k < 300) return g.emb[(size_t)g.xidx[b]*300 + k];
    if (k < 812) return g.A0[b*512 + (k-300)];
    return g.A1[b*512 + (k-812)];
  }
  if (VAR==V_Z2 || VAR==V_HA) {
    if (k < 512) return g.A0[b*512+k];
    return g.A1[b*512 + (k-512)];
  }
  return g.A0[b*512+k]; // V_Q
}

template<int VAR>
__device__ __forceinline__ float loadW(const GArgs& g, int k, int c) {
  if (VAR==V_Z1) return (k<812) ? g.W0[(size_t)k*2048+c] : g.W1[(size_t)(k-812)*2048+c];
  if (VAR==V_Z2) return (k<512) ? g.W0[(size_t)k*2048+c] : g.W1[(size_t)(k-512)*2048+c];
  if (VAR==V_Q)  return (c<512) ? g.W0[(size_t)k*512+c]  : g.W1[(size_t)k*512+(c-512)];
  return g.W0[(size_t)k*512+c]; // V_HA
}

// grid: (N/128, ceil(K/64)); block: 128. One column per thread.
template<int VAR>
__global__ void gemm16_atomic(GArgs g) {
  __shared__ __align__(16) float As[64][16];
  int tid = threadIdx.x;                 // 128
  int col = blockIdx.x*128 + tid;
  int k0  = blockIdx.y*64;

  #pragma unroll
  for (int i=0;i<8;i++) {
    int e = tid + i*128;                 // 0..1023
    int kl = e >> 4, b = e & 15;
    int k = k0 + kl;
    As[kl][b] = (k < g.K) ? loadA<VAR>(g, b, k) : 0.f;
  }
  __syncthreads();

  float acc[16];
  #pragma unroll
  for (int b=0;b<16;b++) acc[b]=0.f;

  #pragma unroll 4
  for (int kl=0; kl<64; kl++) {
    int k = k0 + kl;
    float w = (k < g.K) ? loadW<VAR>(g, k, col) : 0.f;
    const float4* ap = (const float4*)&As[kl][0];
    float4 v0 = ap[0], v1 = ap[1], v2 = ap[2], v3 = ap[3];
    acc[0]  = fmaf(v0.x,w,acc[0]);  acc[1]  = fmaf(v0.y,w,acc[1]);
    acc[2]  = fmaf(v0.z,w,acc[2]);  acc[3]  = fmaf(v0.w,w,acc[3]);
    acc[4]  = fmaf(v1.x,w,acc[4]);  acc[5]  = fmaf(v1.y,w,acc[5]);
    acc[6]  = fmaf(v1.z,w,acc[6]);  acc[7]  = fmaf(v1.w,w,acc[7]);
    acc[8]  = fmaf(v2.x,w,acc[8]);  acc[9]  = fmaf(v2.y,w,acc[9]);
    acc[10] = fmaf(v2.z,w,acc[10]); acc[11] = fmaf(v2.w,w,acc[11]);
    acc[12] = fmaf(v3.x,w,acc[12]); acc[13] = fmaf(v3.y,w,acc[13]);
    acc[14] = fmaf(v3.z,w,acc[14]); acc[15] = fmaf(v3.w,w,acc[15]);
  }
  #pragma unroll
  for (int b=0;b<16;b++)
    atomicAdd(&g.C[(size_t)b*g.N + col], acc[b]);
}

// ---------------- logits: C[16,20000] = ha[16,512] @ Wg + bg (direct write) ----------------
__global__ void gemm16_logits(const float* __restrict__ A, const float* __restrict__ W,
                              const float* __restrict__ bias) {
  __shared__ __align__(16) float As[512][16];   // 32 KB
  int tid = threadIdx.x;                 // 128
  int col = blockIdx.x*128 + tid;
  #pragma unroll
  for (int i=0;i<64;i++) {
    int e = tid + i*128;                 // 0..8191
    int kl = e >> 4, b = e & 15;
    As[kl][b] = A[b*512 + kl];
  }
  __syncthreads();
  if (col >= VV) return;
  float acc[16];
  #pragma unroll
  for (int b=0;b<16;b++) acc[b]=0.f;
  #pragma unroll 4
  for (int k=0; k<512; k++) {
    float w = W[(size_t)k*VV + col];
    const float4* ap = (const float4*)&As[k][0];
    float4 v0 = ap[0], v1 = ap[1], v2 = ap[2], v3 = ap[3];
    acc[0]  = fmaf(v0.x,w,acc[0]);  acc[1]  = fmaf(v0.y,w,acc[1]);
    acc[2]  = fmaf(v0.z,w,acc[2]);  acc[3]  = fmaf(v0.w,w,acc[3]);
    acc[4]  = fmaf(v1.x,w,acc[4]);  acc[5]  = fmaf(v1.y,w,acc[5]);
    acc[6]  = fmaf(v1.z,w,acc[6]);  acc[7]  = fmaf(v1.w,w,acc[7]);
    acc[8]  = fmaf(v2.x,w,acc[8]);  acc[9]  = fmaf(v2.y,w,acc[9]);
    acc[10] = fmaf(v2.z,w,acc[10]); acc[11] = fmaf(v2.w,w,acc[11]);
    acc[12] = fmaf(v3.x,w,acc[12]); acc[13] = fmaf(v3.y,w,acc[13]);
    acc[14] = fmaf(v3.z,w,acc[14]); acc[15] = fmaf(v3.w,w,acc[15]);
  }
  float bv = bias[col];
  #pragma unroll
  for (int b=0;b<16;b++)
    g_logits[(size_t)b*VV + col] = acc[b] + bv;
}

// ---------------- LSTM pointwise ----------------
__global__ void lstm_pw_kernel(const float* __restrict__ z, const float* __restrict__ cin,
                               float* __restrict__ hout, float* __restrict__ cout) {
  int idx = blockIdx.x*blockDim.x + threadIdx.x;
  if (idx >= BB*HH) return;
  int b = idx >> 9, j = idx & 511;
  const float* zb = z + b*2048;
  float iv = sigf(zb[j]);
  float fv = sigf(zb[512+j]);
  float gv = tanhf(zb[1024+j]);
  float ov = sigf(zb[1536+j]);
  float c = fv*cin[idx] + iv*gv;
  hout[idx] = ov*tanhf(c);
  cout[idx] = c;
}

// ---------------- attention scores ----------------
__global__ void scores_kernel(const float* __restrict__ avg, const float* __restrict__ avc) {
  int r = blockIdx.x;            // 0..9599
  int b = r / TT;
  int tid = threadIdx.x;         // 256
  const float* prow = g_P + (size_t)r*1024;
  const float* qb = g_q + b*1024;
  float ag=0.f, ac=0.f;
  for (int j=tid; j<512; j+=256) {
    ag += tanhf(qb[j]     + prow[j])     * avg[j];
    ac += tanhf(qb[512+j] + prow[512+j]) * avc[j];
  }
  #pragma unroll
  for (int o=16;o>0;o>>=1){
    ag += __shfl_down_sync(0xffffffffu, ag, o);
    ac += __shfl_down_sync(0xffffffffu, ac, o);
  }
  __shared__ float rg[8], rc[8];
  int w = tid>>5, l = tid&31;
  if (l==0){ rg[w]=ag; rc[w]=ac; }
  __syncthreads();
  if (tid==0){
    float sg=0.f, sc=0.f;
    #pragma unroll
    for (int i=0;i<8;i++){ sg+=rg[i]; sc+=rc[i]; }
    g_sg[r]=sg; g_sc[r]=sc;
  }
}

// ---------------- softmax over T (both heads) ----------------
__global__ void softmax_kernel() {
  int b = blockIdx.x, tid = threadIdx.x;   // 256
  __shared__ float ag[TT], ac[TT];
  __shared__ float rbuf[256];
  for (int t=tid;t<TT;t+=256){ ag[t]=g_sg[b*TT+t]; ac[t]=g_sc[b*TT+t]; }
  __syncthreads();
  for (int pass=0; pass<2; pass++) {
    float* arr = pass ? ac : ag;
    float mx = -1e30f;
    for (int t=tid;t<TT;t+=256) mx = fmaxf(mx, arr[t]);
    rbuf[tid]=mx; __syncthreads();
    for (int s=128;s>0;s>>=1){ if (tid<s) rbuf[tid]=fmaxf(rbuf[tid],rbuf[tid+s]); __syncthreads(); }
    mx = rbuf[0]; __syncthreads();
    float ls=0.f;
    for (int t=tid;t<TT;t+=256){ float e=expf(arr[t]-mx); arr[t]=e; ls+=e; }
    rbuf[tid]=ls; __syncthreads();
    for (int s=128;s>0;s>>=1){ if (tid<s) rbuf[tid]+=rbuf[tid+s]; __syncthreads(); }
    float inv = 1.0f/rbuf[0]; __syncthreads();
    for (int t=tid;t<TT;t+=256) arr[t]*=inv;
    __syncthreads();
  }
  for (int t=tid;t<TT;t+=256){ g_aligng[b*TT+t]=ag[t]; g_alignc[b*TT+t]=ac[t]; }
}

// ---------------- context = align_g @ enc_outs, T-sliced + atomic ----------------
__global__ void ctx_kernel(const float* __restrict__ enc) {
  int s = blockIdx.x;            // 0..9 (T slices of 60)
  int b = blockIdx.y;
  int tid = threadIdx.x;         // 512
  __shared__ float ag[60];
  if (tid < 60) ag[tid] = g_aligng[b*TT + s*60 + tid];
  __syncthreads();
  const float* eb = enc + (size_t)b*TT*HH + (size_t)(s*60)*HH + tid;
  float a0=0.f,a1=0.f,a2=0.f,a3=0.f,a4=0.f,a5=0.f;
  #pragma unroll 2
  for (int t=0;t<60;t+=6){
    a0 += ag[t]  *eb[(size_t)(t  )*HH];
    a1 += ag[t+1]*eb[(size_t)(t+1)*HH];
    a2 += ag[t+2]*eb[(size_t)(t+2)*HH];
    a3 += ag[t+3]*eb[(size_t)(t+3)*HH];
    a4 += ag[t+4]*eb[(size_t)(t+4)*HH];
    a5 += ag[t+5]*eb[(size_t)(t+5)*HH];
  }
  atomicAdd(&g_ctx[b*HH+tid], (a0+a1)+(a2+a3)+(a4+a5));
}

// ---------------- hidden_att finalize: tanh + switch ----------------
__global__ void ha_finalize_kernel(float* __restrict__ out_hidden,
                                   const float* __restrict__ Wf, const float* __restrict__ bf) {
  int b = blockIdx.x, tid = threadIdx.x;   // 512
  __shared__ float rb[512];
  float t = tanhf(g_ha[b*HH+tid]);
  out_hidden[b*HH+tid] = t;
  rb[tid] = t*Wf[tid];
  __syncthreads();
  for (int s=256;s>0;s>>=1){ if (tid<s) rb[tid]+=rb[tid+s]; __syncthreads(); }
  if (tid==0) g_switch[b] = sigf(rb[0]+bf[0]);
}

// ---------------- vocab softmax reductions ----------------
__global__ void vred_kernel() {
  int b = blockIdx.x, tid = threadIdx.x;   // 1024
  __shared__ float rb[1024];
  const float* lb = g_logits + (size_t)b*VV;
  float mx = -1e30f;
  for (int i=tid;i<VV;i+=1024) mx = fmaxf(mx, lb[i]);
  rb[tid]=mx; __syncthreads();
  for (int s=512;s>0;s>>=1){ if (tid<s) rb[tid]=fmaxf(rb[tid],rb[tid+s]); __syncthreads(); }
  mx = rb[0]; __syncthreads();
  float sm=0.f;
  for (int i=tid;i<VV;i+=1024) sm += expf(lb[i]-mx);
  rb[tid]=sm; __syncthreads();
  for (int s=512;s>0;s>>=1){ if (tid<s) rb[tid]+=rb[tid+s]; __syncthreads(); }
  if (tid==0){ g_vred[b*2]=mx; g_vred[b*2+1]=rb[0]; }
}

// ---------------- final: copy_prob stream + mix ----------------
__global__ void final_kernel(const float* __restrict__ enc_ins, float* __restrict__ result) {
  int b = blockIdx.y, tid = threadIdx.x;   // 256
  int v = blockIdx.x*256 + tid;
  __shared__ float ac[TT];
  for (int t=tid;t<TT;t+=256) ac[t]=g_alignc[b*TT+t];
  __syncthreads();
  if (v >= VV) return;
  const float* eb = enc_ins + (size_t)b*TT*VV + v;
  float a0=0.f,a1=0.f,a2=0.f,a3=0.f,a4=0.f,a5=0.f,a6=0.f,a7=0.f;
  for (int t=0;t<TT;t+=8){
    a0 += ac[t]  * eb[(size_t)(t  )*VV];
    a1 += ac[t+1]* eb[(size_t)(t+1)*VV];
    a2 += ac[t+2]* eb[(size_t)(t+2)*VV];
    a3 += ac[t+3]* eb[(size_t)(t+3)*VV];
    a4 += ac[t+4]* eb[(size_t)(t+4)*VV];
    a5 += ac[t+5]* eb[(size_t)(t+5)*VV];
    a6 += ac[t+6]* eb[(size_t)(t+6)*VV];
    a7 += ac[t+7]* eb[(size_t)(t+7)*VV];
  }
  float copy = ((a0+a1)+(a2+a3))+((a4+a5)+(a6+a7));
  float sw = g_switch[b];
  float mx = g_vred[b*2], sm = g_vred[b*2+1];
  float gen = expf(g_logits[(size_t)b*VV+v]-mx)/sm;
  result[(size_t)b*VV+v] = gen*(1.0f-sw) + copy*sw;
}

// ---------------- launch ----------------
extern "C" void kernel_launch(void* const* d_in, const int* in_sizes, int n_in,
                              void* d_out, int out_size) {
  const int*   x        = (const int*)  d_in[0];
  const float* lha      = (const float*)d_in[1];
  const float* h1       = (const float*)d_in[2];
  const float* c1       = (const float*)d_in[3];
  const float* h2       = (const float*)d_in[4];
  const float* c2       = (const float*)d_in[5];
  const float* enc_outs = (const float*)d_in[6];
  const float* enc_ins  = (const float*)d_in[7];
  const float* emb      = (const float*)d_in[8];
  const float* k1       = (const float*)d_in[9];
  const float* r1       = (const float*)d_in[10];
  const float* b1       = (const float*)d_in[11];
  const float* k2       = (const float*)d_in[12];
  const float* r2       = (const float*)d_in[13];
  const float* b2       = (const float*)d_in[14];
  const float* Wh       = (const float*)d_in[15];
  const float* bh       = (const float*)d_in[16];
  const float* Wg       = (const float*)d_in[17];
  const float* bg       = (const float*)d_in[18];
  const float* Wf       = (const float*)d_in[19];
  const float* bf       = (const float*)d_in[20];
  const float* aw1g     = (const float*)d_in[21];
  const float* aw2g     = (const float*)d_in[22];
  const float* avg      = (const float*)d_in[23];
  const float* aw1c     = (const float*)d_in[24];
  const float* aw2c     = (const float*)d_in[25];
  const float* avc      = (const float*)d_in[26];

  float* out = (float*)d_out;
  float* out_result = out;                       // 16*20000
  float* out_hidden = out + BB*VV;
  float* out_h1n    = out_hidden + BB*HH;
  float* out_c1n    = out_h1n + BB*HH;
  float* out_h2n    = out_c1n + BB*HH;
  float* out_c2n    = out_h2n + BB*HH;

  float *p_z1, *p_z2, *p_q, *p_ctx, *p_ha;
  cudaGetSymbolAddress((void**)&p_z1, g_z1);
  cudaGetSymbolAddress((void**)&p_z2, g_z2);
  cudaGetSymbolAddress((void**)&p_q, g_q);
  cudaGetSymbolAddress((void**)&p_ctx, g_ctx);
  cudaGetSymbolAddress((void**)&p_ha, g_ha);

  init_kernel<<<(98304+255)/256, 256>>>(b1, b2, bh);

  // Big independent GEMM: P = enc_outs @ [aw2g | aw2c]
  sgemm_attn_kernel<<<dim3(75,8), 256>>>(enc_outs, aw2g, aw2c);

  // LSTM 1: z1 += [emb, lha, h1] @ [k1; r1]
  GArgs az1; az1.A0=lha; az1.A1=h1; az1.W0=k1; az1.W1=r1;
  az1.xidx=x; az1.emb=emb; az1.C=p_z1; az1.K=1324; az1.N=2048;
  gemm16_atomic<V_Z1><<<dim3(16,21),128>>>(az1);
  lstm_pw_kernel<<<32,256>>>(p_z1, c1, out_h1n, out_c1n);

  // LSTM 2
  GArgs az2; az2.A0=out_h1n; az2.A1=h2; az2.W0=k2; az2.W1=r2;
  az2.xidx=nullptr; az2.emb=nullptr; az2.C=p_z2; az2.K=1024; az2.N=2048;
  gemm16_atomic<V_Z2><<<dim3(16,16),128>>>(az2);
  lstm_pw_kernel<<<32,256>>>(p_z2, c2, out_h2n, out_c2n);

  // queries (both heads)
  GArgs aq; aq.A0=out_h2n; aq.A1=nullptr; aq.W0=aw1g; aq.W1=aw1c;
  aq.xidx=nullptr; aq.emb=nullptr; aq.C=p_q; aq.K=512; aq.N=1024;
  gemm16_atomic<V_Q><<<dim3(8,8),128>>>(aq);

  scores_kernel<<<BT,256>>>(avg, avc);
  softmax_kernel<<<BB,256>>>();
  ctx_kernel<<<dim3(10,BB),512>>>(enc_outs);

  // hidden_att accum: g_ha += [ctx, h2n] @ Wh   (bias preloaded, tanh in finalize)
  GArgs aha; aha.A0=p_ctx; aha.A1=out_h2n; aha.W0=Wh; aha.W1=nullptr;
  aha.xidx=nullptr; aha.emb=nullptr; aha.C=p_ha; aha.K=1024; aha.N=512;
  gemm16_atomic<V_HA><<<dim3(4,16),128>>>(aha);
  ha_finalize_kernel<<<BB,512>>>(out_hidden, Wf, bf);

  gemm16_logits<<<(VV+127)/128,128>>>(out_hidden, Wg, bg);
  vred_kernel<<<BB,1024>>>();

  final_kernel<<<dim3((VV+255)/256, BB), 256>>>(enc_ins, out_result);
}

// round 6
// speedup vs baseline: 1.2205x; 1.2205x over previous
#include <cuda_runtime.h>
#include <cuda_bf16.h>
#include <math.h>
#include <stdint.h>

#define BB 16
#define TT 600
#define VV 20000
#define EE 300
#define HH 512
#define BT (BB*TT)   // 9600

// ---------------- scratch ----------------
__device__ float g_P[(size_t)BT*1024];   // [9600][1024]: 0..511 = enc@aw2g, 512..1023 = enc@aw2c
__device__ uint32_t g_A2h[(size_t)BT*256];   // enc hi, bf16 [9600][512] packed as u32
__device__ uint32_t g_A2l[(size_t)BT*256];   // enc lo
__device__ uint32_t g_Wth[1024*256];         // W^T hi, bf16 [1024 n][512 k]
__device__ uint32_t g_Wtl[1024*256];         // W^T lo
__device__ float g_z1[BB*2048];
__device__ float g_z2[BB*2048];
__device__ float g_q[BB*1024];
__device__ float g_ha[BB*HH];
__device__ float g_sg[BB*TT];
__device__ float g_sc[BB*TT];
__device__ float g_aligng[BB*TT];
__device__ float g_alignc[BB*TT];
__device__ float g_ctx[BB*HH];
__device__ float g_logits[(size_t)BB*VV];
__device__ float g_vred[BB*2];
__device__ float g_switch[BB];

__device__ __forceinline__ float sigf(float x){ return 1.0f/(1.0f+expf(-x)); }

// ---------------- init: write biases / zeros into accumulators ----------------
__global__ void init_kernel(const float* __restrict__ b1, const float* __restrict__ b2,
                            const float* __restrict__ bh) {
  int idx = blockIdx.x*blockDim.x + threadIdx.x;
  if (idx < 32768)            g_z1[idx] = b1[idx & 2047];
  else if (idx < 65536)       g_z2[idx-32768] = b2[idx & 2047];
  else if (idx < 81920)       g_q[idx-65536] = 0.f;
  else if (idx < 90112)       g_ha[idx-81920] = bh[idx & 511];
  else if (idx < 98304)       g_ctx[idx-90112] = 0.f;
}

// ---------------- convert enc_outs -> bf16 hi/lo ----------------
__global__ void convA_kernel(const float* __restrict__ A) {
  int i4 = blockIdx.x*blockDim.x + threadIdx.x;   // one float4 per thread
  if (i4 >= BT*512/4) return;
  float4 v = *(const float4*)&A[i4*4];
  __nv_bfloat16 h0 = __float2bfloat16(v.x);
  __nv_bfloat16 h1 = __float2bfloat16(v.y);
  __nv_bfloat16 h2 = __float2bfloat16(v.z);
  __nv_bfloat16 h3 = __float2bfloat16(v.w);
  __nv_bfloat16 l0 = __float2bfloat16(v.x - __bfloat162float(h0));
  __nv_bfloat16 l1 = __float2bfloat16(v.y - __bfloat162float(h1));
  __nv_bfloat16 l2 = __float2bfloat16(v.z - __bfloat162float(h2));
  __nv_bfloat16 l3 = __float2bfloat16(v.w - __bfloat162float(h3));
  __nv_bfloat162* ph = (__nv_bfloat162*)g_A2h;
  __nv_bfloat162* pl = (__nv_bfloat162*)g_A2l;
  ph[i4*2]   = __nv_bfloat162(h0,h1);
  ph[i4*2+1] = __nv_bfloat162(h2,h3);
  pl[i4*2]   = __nv_bfloat162(l0,l1);
  pl[i4*2+1] = __nv_bfloat162(l2,l3);
}

// ---------------- transpose + convert W[512,512]x2 -> Wt[1024][512] bf16 hi/lo ----------------
__global__ void convW_kernel(const float* __restrict__ Wg, const float* __restrict__ Wc) {
  __shared__ float tile[32][33];
  int k0 = blockIdx.x*32;      // 16 blocks
  int n0 = blockIdx.y*32;      // 32 blocks
  const float* W = (n0 < 512) ? Wg : Wc;
  int nn0 = n0 & 511;
  int tx = threadIdx.x & 31, ty = threadIdx.x >> 5;   // 256 threads = 32x8
  #pragma unroll
  for (int i=0;i<4;i++) {
    int k = k0 + ty + i*8;
    tile[ty+i*8][tx] = W[(size_t)k*512 + nn0 + tx];
  }
  __syncthreads();
  __nv_bfloat16* WH = (__nv_bfloat16*)g_Wth;
  __nv_bfloat16* WL = (__nv_bfloat16*)g_Wtl;
  #pragma unroll
  for (int i=0;i<4;i++) {
    int n = n0 + ty + i*8;
    float x = tile[tx][ty+i*8];
    __nv_bfloat16 h = __float2bfloat16(x);
    WH[(size_t)n*512 + k0 + tx] = h;
    WL[(size_t)n*512 + k0 + tx] = __float2bfloat16(x - __bfloat162float(h));
  }
}

// ---------------- tensor-core GEMM: g_P[9600,1024] = enc @ [aw2g|aw2c], 3xBF16 split ----------------
__device__ __forceinline__ void mma16816(float* c, const uint32_t* a, const uint32_t* b) {
  asm volatile(
    "mma.sync.aligned.m16n8k16.row.col.f32.bf16.bf16.f32 "
    "{%0,%1,%2,%3}, {%4,%5,%6,%7}, {%8,%9}, {%0,%1,%2,%3};"
    : "+f"(c[0]), "+f"(c[1]), "+f"(c[2]), "+f"(c[3])
    : "r"(a[0]), "r"(a[1]), "r"(a[2]), "r"(a[3]), "r"(b[0]), "r"(b[1]));
}

__global__ void __launch_bounds__(256) mma_attn_kernel() {
  // block tile 128(M) x 128(N); 8 warps: 4(M) x 2(N); warp tile 32x64
  __shared__ uint32_t sAh[128*20];   // [128 rows][40 bf16] padded
  __shared__ uint32_t sAl[128*20];
  __shared__ uint32_t sBh[128*20];
  __shared__ uint32_t sBl[128*20];

  int tid = threadIdx.x;
  int bm = blockIdx.x * 128;     // 75
  int bn = blockIdx.y * 128;     // 8
  int wid = tid >> 5, lane = tid & 31;
  int wm = wid >> 1, wn = wid & 1;
  int g = lane >> 2, t4 = lane & 3;

  float acc[2][8][4];
  #pragma unroll
  for (int mt=0;mt<2;mt++)
    #pragma unroll
    for (int nt=0;nt<8;nt++)
      #pragma unroll
      for (int r=0;r<4;r++) acc[mt][nt][r]=0.f;

  for (int kc=0; kc<512; kc+=32) {
    // load chunk: A rows bm..bm+127, B rows bn..bn+127, k = kc..kc+31 (16 u32 each)
    #pragma unroll
    for (int i=0;i<8;i++) {
      int e = tid + i*256;            // 0..2047
      int row = e >> 4, kw = e & 15;
      size_t ga = (size_t)(bm+row)*256 + (kc>>1) + kw;
      size_t gb = (size_t)(bn+row)*256 + (kc>>1) + kw;
      int ss = row*20 + kw;
      sAh[ss] = g_A2h[ga];
      sAl[ss] = g_A2l[ga];
      sBh[ss] = g_Wth[gb];
      sBl[ss] = g_Wtl[gb];
    }
    __syncthreads();

    #pragma unroll
    for (int ks=0; ks<2; ks++) {
      int kbw = ks*8;
      uint32_t ah[2][4], al[2][4];
      #pragma unroll
      for (int mt=0;mt<2;mt++) {
        int r0 = (wm*32 + mt*16 + g)*20 + kbw + t4;
        int r8 = r0 + 8*20;
        ah[mt][0]=sAh[r0];   ah[mt][1]=sAh[r8];
        ah[mt][2]=sAh[r0+4]; ah[mt][3]=sAh[r8+4];
        al[mt][0]=sAl[r0];   al[mt][1]=sAl[r8];
        al[mt][2]=sAl[r0+4]; al[mt][3]=sAl[r8+4];
      }
      #pragma unroll
      for (int nt=0;nt<8;nt++) {
        int n0 = (wn*64 + nt*8 + g)*20 + kbw + t4;
        uint32_t bh[2], bl[2];
        bh[0]=sBh[n0]; bh[1]=sBh[n0+4];
        bl[0]=sBl[n0]; bl[1]=sBl[n0+4];
        #pragma unroll
        for (int mt=0;mt<2;mt++) {
          mma16816(acc[mt][nt], ah[mt], bh);
          mma16816(acc[mt][nt], ah[mt], bl);
          mma16816(acc[mt][nt], al[mt], bh);
        }
      }
    }
    __syncthreads();
  }

  // epilogue: write P (fp32)
  #pragma unroll
  for (int mt=0;mt<2;mt++) {
    int row0 = bm + wm*32 + mt*16 + g;
    #pragma unroll
    for (int nt=0;nt<8;nt++) {
      int col = bn + wn*64 + nt*8 + t4*2;
      *(float2*)&g_P[(size_t)row0*1024 + col]     = make_float2(acc[mt][nt][0], acc[mt][nt][1]);
      *(float2*)&g_P[(size_t)(row0+8)*1024 + col] = make_float2(acc[mt][nt][2], acc[mt][nt][3]);
    }
  }
}

// ---------------- small-M GEMM, K-split + atomic accumulate ----------------
struct GArgs {
  const float* A0; const float* A1;
  const float* W0; const float* W1;
  const int* xidx; const float* emb;
  float* C;
  int K; int N;
};

enum { V_Z1=0, V_Z2=1, V_Q=2, V_HA=3 };

template<int VAR>
__device__ __forceinline__ float loadA(const GArgs& g, int b, int k) {
  if (VAR==V_Z1) {
    if (k < 300) return g.emb[(size_t)g.xidx[b]*300 + k];
    if (k < 812) return g.A0[b*512 + (k-300)];
    return g.A1[b*512 + (k-812)];
  }
  if (VAR==V_Z2 || VAR==V_HA) {
    if (k < 512) return g.A0[b*512+k];
    return g.A1[b*512 + (k-512)];
  }
  return g.A0[b*512+k]; // V_Q
}

template<int VAR>
__device__ __forceinline__ float loadW(const GArgs& g, int k, int c) {
  if (VAR==V_Z1) return (k<812) ? g.W0[(size_t)k*2048+c] : g.W1[(size_t)(k-812)*2048+c];
  if (VAR==V_Z2) return (k<512) ? g.W0[(size_t)k*2048+c] : g.W1[(size_t)(k-512)*2048+c];
  if (VAR==V_Q)  return (c<512) ? g.W0[(size_t)k*512+c]  : g.W1[(size_t)k*512+(c-512)];
  return g.W0[(size_t)k*512+c]; // V_HA
}

template<int VAR>
__global__ void gemm16_atomic(GArgs g) {
  __shared__ __align__(16) float As[64][16];
  int tid = threadIdx.x;                 // 128
  int col = blockIdx.x*128 + tid;
  int k0  = blockIdx.y*64;

  #pragma unroll
  for (int i=0;i<8;i++) {
    int e = tid + i*128;
    int kl = e >> 4, b = e & 15;
    int k = k0 + kl;
    As[kl][b] = (k < g.K) ? loadA<VAR>(g, b, k) : 0.f;
  }
  __syncthreads();

  float acc[16];
  #pragma unroll
  for (int b=0;b<16;b++) acc[b]=0.f;

  #pragma unroll 4
  for (int kl=0; kl<64; kl++) {
    int k = k0 + kl;
    float w = (k < g.K) ? loadW<VAR>(g, k, col) : 0.f;
    const float4* ap = (const float4*)&As[kl][0];
    float4 v0 = ap[0], v1 = ap[1], v2 = ap[2], v3 = ap[3];
    acc[0]  = fmaf(v0.x,w,acc[0]);  acc[1]  = fmaf(v0.y,w,acc[1]);
    acc[2]  = fmaf(v0.z,w,acc[2]);  acc[3]  = fmaf(v0.w,w,acc[3]);
    acc[4]  = fmaf(v1.x,w,acc[4]);  acc[5]  = fmaf(v1.y,w,acc[5]);
    acc[6]  = fmaf(v1.z,w,acc[6]);  acc[7]  = fmaf(v1.w,w,acc[7]);
    acc[8]  = fmaf(v2.x,w,acc[8]);  acc[9]  = fmaf(v2.y,w,acc[9]);
    acc[10] = fmaf(v2.z,w,acc[10]); acc[11] = fmaf(v2.w,w,acc[11]);
    acc[12] = fmaf(v3.x,w,acc[12]); acc[13] = fmaf(v3.y,w,acc[13]);
    acc[14] = fmaf(v3.z,w,acc[14]); acc[15] = fmaf(v3.w,w,acc[15]);
  }
  #pragma unroll
  for (int b=0;b<16;b++)
    atomicAdd(&g.C[(size_t)b*g.N + col], acc[b]);
}

// ---------------- logits: C[16,20000] = ha[16,512] @ Wg + bg ----------------
__global__ void gemm16_logits(const float* __restrict__ A, const float* __restrict__ W,
                              const float* __restrict__ bias) {
  __shared__ __align__(16) float As[512][16];
  int tid = threadIdx.x;                 // 128
  int col = blockIdx.x*128 + tid;
  #pragma unroll
  for (int i=0;i<64;i++) {
    int e = tid + i*128;
    int kl = e >> 4, b = e & 15;
    As[kl][b] = A[b*512 + kl];
  }
  __syncthreads();
  if (col >= VV) return;
  float acc[16];
  #pragma unroll
  for (int b=0;b<16;b++) acc[b]=0.f;
  #pragma unroll 4
  for (int k=0; k<512; k++) {
    float w = W[(size_t)k*VV + col];
    const float4* ap = (const float4*)&As[k][0];
    float4 v0 = ap[0], v1 = ap[1], v2 = ap[2], v3 = ap[3];
    acc[0]  = fmaf(v0.x,w,acc[0]);  acc[1]  = fmaf(v0.y,w,acc[1]);
    acc[2]  = fmaf(v0.z,w,acc[2]);  acc[3]  = fmaf(v0.w,w,acc[3]);
    acc[4]  = fmaf(v1.x,w,acc[4]);  acc[5]  = fmaf(v1.y,w,acc[5]);
    acc[6]  = fmaf(v1.z,w,acc[6]);  acc[7]  = fmaf(v1.w,w,acc[7]);
    acc[8]  = fmaf(v2.x,w,acc[8]);  acc[9]  = fmaf(v2.y,w,acc[9]);
    acc[10] = fmaf(v2.z,w,acc[10]); acc[11] = fmaf(v2.w,w,acc[11]);
    acc[12] = fmaf(v3.x,w,acc[12]); acc[13] = fmaf(v3.y,w,acc[13]);
    acc[14] = fmaf(v3.z,w,acc[14]); acc[15] = fmaf(v3.w,w,acc[15]);
  }
  float bv = bias[col];
  #pragma unroll
  for (int b=0;b<16;b++)
    g_logits[(size_t)b*VV + col] = acc[b] + bv;
}

// ---------------- LSTM pointwise ----------------
__global__ void lstm_pw_kernel(const float* __restrict__ z, const float* __restrict__ cin,
                               float* __restrict__ hout, float* __restrict__ cout) {
  int idx = blockIdx.x*blockDim.x + threadIdx.x;
  if (idx >= BB*HH) return;
  int b = idx >> 9, j = idx & 511;
  const float* zb = z + b*2048;
  float iv = sigf(zb[j]);
  float fv = sigf(zb[512+j]);
  float gv = tanhf(zb[1024+j]);
  float ov = sigf(zb[1536+j]);
  float c = fv*cin[idx] + iv*gv;
  hout[idx] = ov*tanhf(c);
  cout[idx] = c;
}

// ---------------- attention scores ----------------
__global__ void scores_kernel(const float* __restrict__ avg, const float* __restrict__ avc) {
  int r = blockIdx.x;            // 0..9599
  int b = r / TT;
  int tid = threadIdx.x;         // 256
  const float* prow = g_P + (size_t)r*1024;
  const float* qb = g_q + b*1024;
  float ag=0.f, ac=0.f;
  for (int j=tid; j<512; j+=256) {
    ag += tanhf(qb[j]     + prow[j])     * avg[j];
    ac += tanhf(qb[512+j] + prow[512+j]) * avc[j];
  }
  #pragma unroll
  for (int o=16;o>0;o>>=1){
    ag += __shfl_down_sync(0xffffffffu, ag, o);
    ac += __shfl_down_sync(0xffffffffu, ac, o);
  }
  __shared__ float rg[8], rc[8];
  int w = tid>>5, l = tid&31;
  if (l==0){ rg[w]=ag; rc[w]=ac; }
  __syncthreads();
  if (tid==0){
    float sg=0.f, sc=0.f;
    #pragma unroll
    for (int i=0;i<8;i++){ sg+=rg[i]; sc+=rc[i]; }
    g_sg[r]=sg; g_sc[r]=sc;
  }
}

// ---------------- softmax over T (both heads) ----------------
__global__ void softmax_kernel() {
  int b = blockIdx.x, tid = threadIdx.x;   // 256
  __shared__ float ag[TT], ac[TT];
  __shared__ float rbuf[256];
  for (int t=tid;t<TT;t+=256){ ag[t]=g_sg[b*TT+t]; ac[t]=g_sc[b*TT+t]; }
  __syncthreads();
  for (int pass=0; pass<2; pass++) {
    float* arr = pass ? ac : ag;
    float mx = -1e30f;
    for (int t=tid;t<TT;t+=256) mx = fmaxf(mx, arr[t]);
    rbuf[tid]=mx; __syncthreads();
    for (int s=128;s>0;s>>=1){ if (tid<s) rbuf[tid]=fmaxf(rbuf[tid],rbuf[tid+s]); __syncthreads(); }
    mx = rbuf[0]; __syncthreads();
    float ls=0.f;
    for (int t=tid;t<TT;t+=256){ float e=expf(arr[t]-mx); arr[t]=e; ls+=e; }
    rbuf[tid]=ls; __syncthreads();
    for (int s=128;s>0;s>>=1){ if (tid<s) rbuf[tid]+=rbuf[tid+s]; __syncthreads(); }
    float inv = 1.0f/rbuf[0]; __syncthreads();
    for (int t=tid;t<TT;t+=256) arr[t]*=inv;
    __syncthreads();
  }
  for (int t=tid;t<TT;t+=256){ g_aligng[b*TT+t]=ag[t]; g_alignc[b*TT+t]=ac[t]; }
}

// ---------------- context = align_g @ enc_outs, T-sliced + atomic ----------------
__global__ void ctx_kernel(const float* __restrict__ enc) {
  int s = blockIdx.x;            // 0..9
  int b = blockIdx.y;
  int tid = threadIdx.x;         // 512
  __shared__ float ag[60];
  if (tid < 60) ag[tid] = g_aligng[b*TT + s*60 + tid];
  __syncthreads();
  const float* eb = enc + (size_t)b*TT*HH + (size_t)(s*60)*HH + tid;
  float a0=0.f,a1=0.f,a2=0.f,a3=0.f,a4=0.f,a5=0.f;
  #pragma unroll 2
  for (int t=0;t<60;t+=6){
    a0 += ag[t]  *eb[(size_t)(t  )*HH];
    a1 += ag[t+1]*eb[(size_t)(t+1)*HH];
    a2 += ag[t+2]*eb[(size_t)(t+2)*HH];
    a3 += ag[t+3]*eb[(size_t)(t+3)*HH];
    a4 += ag[t+4]*eb[(size_t)(t+4)*HH];
    a5 += ag[t+5]*eb[(size_t)(t+5)*HH];
  }
  atomicAdd(&g_ctx[b*HH+tid], (a0+a1)+(a2+a3)+(a4+a5));
}

// ---------------- hidden_att finalize: tanh + switch ----------------
__global__ void ha_finalize_kernel(float* __restrict__ out_hidden,
                                   const float* __restrict__ Wf, const float* __restrict__ bf) {
  int b = blockIdx.x, tid = threadIdx.x;   // 512
  __shared__ float rb[512];
  float t = tanhf(g_ha[b*HH+tid]);
  out_hidden[b*HH+tid] = t;
  rb[tid] = t*Wf[tid];
  __syncthreads();
  for (int s=256;s>0;s>>=1){ if (tid<s) rb[tid]+=rb[tid+s]; __syncthreads(); }
  if (tid==0) g_switch[b] = sigf(rb[0]+bf[0]);
}

// ---------------- vocab softmax reductions ----------------
__global__ void vred_kernel() {
  int b = blockIdx.x, tid = threadIdx.x;   // 1024
  __shared__ float rb[1024];
  const float* lb = g_logits + (size_t)b*VV;
  float mx = -1e30f;
  for (int i=tid;i<VV;i+=1024) mx = fmaxf(mx, lb[i]);
  rb[tid]=mx; __syncthreads();
  for (int s=512;s>0;s>>=1){ if (tid<s) rb[tid]=fmaxf(rb[tid],rb[tid+s]); __syncthreads(); }
  mx = rb[0]; __syncthreads();
  float sm=0.f;
  for (int i=tid;i<VV;i+=1024) sm += expf(lb[i]-mx);
  rb[tid]=sm; __syncthreads();
  for (int s=512;s>0;s>>=1){ if (tid<s) rb[tid]+=rb[tid+s]; __syncthreads(); }
  if (tid==0){ g_vred[b*2]=mx; g_vred[b*2+1]=rb[0]; }
}

// ---------------- final: copy_prob stream + mix ----------------
__global__ void final_kernel(const float* __restrict__ enc_ins, float* __restrict__ result) {
  int b = blockIdx.y, tid = threadIdx.x;   // 256
  int v = blockIdx.x*256 + tid;
  __shared__ float ac[TT];
  for (int t=tid;t<TT;t+=256) ac[t]=g_alignc[b*TT+t];
  __syncthreads();
  if (v >= VV) return;
  const float* eb = enc_ins + (size_t)b*TT*VV + v;
  float a0=0.f,a1=0.f,a2=0.f,a3=0.f,a4=0.f,a5=0.f,a6=0.f,a7=0.f;
  for (int t=0;t<TT;t+=8){
    a0 += ac[t]  * eb[(size_t)(t  )*VV];
    a1 += ac[t+1]* eb[(size_t)(t+1)*VV];
    a2 += ac[t+2]* eb[(size_t)(t+2)*VV];
    a3 += ac[t+3]* eb[(size_t)(t+3)*VV];
    a4 += ac[t+4]* eb[(size_t)(t+4)*VV];
    a5 += ac[t+5]* eb[(size_t)(t+5)*VV];
    a6 += ac[t+6]* eb[(size_t)(t+6)*VV];
    a7 += ac[t+7]* eb[(size_t)(t+7)*VV];
  }
  float copy = ((a0+a1)+(a2+a3))+((a4+a5)+(a6+a7));
  float sw = g_switch[b];
  float mx = g_vred[b*2], sm = g_vred[b*2+1];
  float gen = expf(g_logits[(size_t)b*VV+v]-mx)/sm;
  result[(size_t)b*VV+v] = gen*(1.0f-sw) + copy*sw;
}

// ---------------- launch ----------------
extern "C" void kernel_launch(void* const* d_in, const int* in_sizes, int n_in,
                              void* d_out, int out_size) {
  const int*   x        = (const int*)  d_in[0];
  const float* lha      = (const float*)d_in[1];
  const float* h1       = (const float*)d_in[2];
  const float* c1       = (const float*)d_in[3];
  const float* h2       = (const float*)d_in[4];
  const float* c2       = (const float*)d_in[5];
  const float* enc_outs = (const float*)d_in[6];
  const float* enc_ins  = (const float*)d_in[7];
  const float* emb      = (const float*)d_in[8];
  const float* k1       = (const float*)d_in[9];
  const float* r1       = (const float*)d_in[10];
  const float* b1       = (const float*)d_in[11];
  const float* k2       = (const float*)d_in[12];
  const float* r2       = (const float*)d_in[13];
  const float* b2       = (const float*)d_in[14];
  const float* Wh       = (const float*)d_in[15];
  const float* bh       = (const float*)d_in[16];
  const float* Wg       = (const float*)d_in[17];
  const float* bg       = (const float*)d_in[18];
  const float* Wf       = (const float*)d_in[19];
  const float* bf       = (const float*)d_in[20];
  const float* aw1g     = (const float*)d_in[21];
  const float* aw2g     = (const float*)d_in[22];
  const float* avg      = (const float*)d_in[23];
  const float* aw1c     = (const float*)d_in[24];
  const float* aw2c     = (const float*)d_in[25];
  const float* avc      = (const float*)d_in[26];

  float* out = (float*)d_out;
  float* out_result = out;                       // 16*20000
  float* out_hidden = out + BB*VV;
  float* out_h1n    = out_hidden + BB*HH;
  float* out_c1n    = out_h1n + BB*HH;
  float* out_h2n    = out_c1n + BB*HH;
  float* out_c2n    = out_h2n + BB*HH;

  float *p_z1, *p_z2, *p_q, *p_ctx, *p_ha;
  cudaGetSymbolAddress((void**)&p_z1, g_z1);
  cudaGetSymbolAddress((void**)&p_z2, g_z2);
  cudaGetSymbolAddress((void**)&p_q, g_q);
  cudaGetSymbolAddress((void**)&p_ctx, g_ctx);
  cudaGetSymbolAddress((void**)&p_ha, g_ha);

  init_kernel<<<(98304+255)/256, 256>>>(b1, b2, bh);

  // convert inputs for tensor-core GEMM
  convA_kernel<<<(BT*512/4 + 255)/256, 256>>>(enc_outs);
  convW_kernel<<<dim3(16,32), 256>>>(aw2g, aw2c);

  // Big GEMM on tensor cores: P = enc_outs @ [aw2g | aw2c] (3x bf16 split)
  mma_attn_kernel<<<dim3(75,8), 256>>>();

  // LSTM 1
  GArgs az1; az1.A0=lha; az1.A1=h1; az1.W0=k1; az1.W1=r1;
  az1.xidx=x; az1.emb=emb; az1.C=p_z1; az1.K=1324; az1.N=2048;
  gemm16_atomic<V_Z1><<<dim3(16,21),128>>>(az1);
  lstm_pw_kernel<<<32,256>>>(p_z1, c1, out_h1n, out_c1n);

  // LSTM 2
  GArgs az2; az2.A0=out_h1n; az2.A1=h2; az2.W0=k2; az2.W1=r2;
  az2.xidx=nullptr; az2.emb=nullptr; az2.C=p_z2; az2.K=1024; az2.N=2048;
  gemm16_atomic<V_Z2><<<dim3(16,16),128>>>(az2);
  lstm_pw_kernel<<<32,256>>>(p_z2, c2, out_h2n, out_c2n);

  // queries (both heads)
  GArgs aq; aq.A0=out_h2n; aq.A1=nullptr; aq.W0=aw1g; aq.W1=aw1c;
  aq.xidx=nullptr; aq.emb=nullptr; aq.C=p_q; aq.K=512; aq.N=1024;
  gemm16_atomic<V_Q><<<dim3(8,8),128>>>(aq);

  scores_kernel<<<BT,256>>>(avg, avc);
  softmax_kernel<<<BB,256>>>();
  ctx_kernel<<<dim3(10,BB),512>>>(enc_outs);

  GArgs aha; aha.A0=p_ctx; aha.A1=out_h2n; aha.W0=Wh; aha.W1=nullptr;
  aha.xidx=nullptr; aha.emb=nullptr; aha.C=p_ha; aha.K=1024; aha.N=512;
  gemm16_atomic<V_HA><<<dim3(4,16),128>>>(aha);
  ha_finalize_kernel<<<BB,512>>>(out_hidden, Wf, bf);

  gemm16_logits<<<(VV+127)/128,128>>>(out_hidden, Wg, bg);
  vred_kernel<<<BB,1024>>>();

  final_kernel<<<dim3((VV+255)/256, BB), 256>>>(enc_ins, out_result);
}

// round 7
// speedup vs baseline: 1.4723x; 1.2062x over previous
#include <cuda_runtime.h>
#include <cuda_bf16.h>
#include <math.h>
#include <stdint.h>

#define BB 16
#define TT 600
#define VV 20000
#define EE 300
#define HH 512
#define BT (BB*TT)   // 9600

// ---------------- scratch ----------------
__device__ uint32_t g_A2h[(size_t)BT*256];   // enc hi, bf16 [9600][512] packed as u32
__device__ uint32_t g_A2l[(size_t)BT*256];   // enc lo
__device__ uint32_t g_Wth[1024*256];         // W^T hi, bf16 [1024 n][512 k]
__device__ uint32_t g_Wtl[1024*256];         // W^T lo
__device__ float g_z1[BB*2048];
__device__ float g_z2[BB*2048];
__device__ float g_q[BB*1024];
__device__ float g_ha[BB*HH];
__device__ float g_sg[BB*TT];
__device__ float g_sc[BB*TT];
__device__ float g_aligng[BB*TT];
__device__ float g_alignc[BB*TT];
__device__ float g_ctx[BB*HH];
__device__ float g_logits[(size_t)BB*VV];
__device__ float g_pm[BB*10];
__device__ float g_ps[BB*10];
__device__ float g_vred[BB*2];
__device__ float g_switch[BB];

__device__ __forceinline__ float sigf(float x){ return 1.0f/(1.0f+expf(-x)); }

// ---------------- init: biases / zeros into accumulators ----------------
// ranges: z1 32768 | z2 32768 | q 16384 | ha 8192 | ctx 8192 | sg 9600 | sc 9600 | logits 320000
#define INIT_TOTAL (117504 + 320000)
__global__ void init_kernel(const float* __restrict__ b1, const float* __restrict__ b2,
                            const float* __restrict__ bh, const float* __restrict__ bg) {
  int idx = blockIdx.x*blockDim.x + threadIdx.x;
  if (idx < 32768)            g_z1[idx] = b1[idx & 2047];
  else if (idx < 65536)       g_z2[idx-32768] = b2[idx & 2047];
  else if (idx < 81920)       g_q[idx-65536] = 0.f;
  else if (idx < 90112)       g_ha[idx-81920] = bh[idx & 511];
  else if (idx < 98304)       g_ctx[idx-90112] = 0.f;
  else if (idx < 107904)      g_sg[idx-98304] = 0.f;
  else if (idx < 117504)      g_sc[idx-107904] = 0.f;
  else if (idx < INIT_TOTAL) {
    int e = idx - 117504;
    g_logits[e] = bg[e % VV];
  }
}

// ---------------- convert enc_outs -> bf16 hi/lo ----------------
__global__ void convA_kernel(const float* __restrict__ A) {
  int i4 = blockIdx.x*blockDim.x + threadIdx.x;
  if (i4 >= BT*512/4) return;
  float4 v = *(const float4*)&A[i4*4];
  __nv_bfloat16 h0 = __float2bfloat16(v.x);
  __nv_bfloat16 h1 = __float2bfloat16(v.y);
  __nv_bfloat16 h2 = __float2bfloat16(v.z);
  __nv_bfloat16 h3 = __float2bfloat16(v.w);
  __nv_bfloat16 l0 = __float2bfloat16(v.x - __bfloat162float(h0));
  __nv_bfloat16 l1 = __float2bfloat16(v.y - __bfloat162float(h1));
  __nv_bfloat16 l2 = __float2bfloat16(v.z - __bfloat162float(h2));
  __nv_bfloat16 l3 = __float2bfloat16(v.w - __bfloat162float(h3));
  __nv_bfloat162* ph = (__nv_bfloat162*)g_A2h;
  __nv_bfloat162* pl = (__nv_bfloat162*)g_A2l;
  ph[i4*2]   = __nv_bfloat162(h0,h1);
  ph[i4*2+1] = __nv_bfloat162(h2,h3);
  pl[i4*2]   = __nv_bfloat162(l0,l1);
  pl[i4*2+1] = __nv_bfloat162(l2,l3);
}

// ---------------- transpose + convert W -> Wt bf16 hi/lo ----------------
__global__ void convW_kernel(const float* __restrict__ Wg, const float* __restrict__ Wc) {
  __shared__ float tile[32][33];
  int k0 = blockIdx.x*32;
  int n0 = blockIdx.y*32;
  const float* W = (n0 < 512) ? Wg : Wc;
  int nn0 = n0 & 511;
  int tx = threadIdx.x & 31, ty = threadIdx.x >> 5;
  #pragma unroll
  for (int i=0;i<4;i++) {
    int k = k0 + ty + i*8;
    tile[ty+i*8][tx] = W[(size_t)k*512 + nn0 + tx];
  }
  __syncthreads();
  __nv_bfloat16* WH = (__nv_bfloat16*)g_Wth;
  __nv_bfloat16* WL = (__nv_bfloat16*)g_Wtl;
  #pragma unroll
  for (int i=0;i<4;i++) {
    int n = n0 + ty + i*8;
    float x = tile[tx][ty+i*8];
    __nv_bfloat16 h = __float2bfloat16(x);
    WH[(size_t)n*512 + k0 + tx] = h;
    WL[(size_t)n*512 + k0 + tx] = __float2bfloat16(x - __bfloat162float(h));
  }
}

// ---------------- mma helpers ----------------
__device__ __forceinline__ void mma16816(float* c, const uint32_t* a, const uint32_t* b) {
  asm volatile(
    "mma.sync.aligned.m16n8k16.row.col.f32.bf16.bf16.f32 "
    "{%0,%1,%2,%3}, {%4,%5,%6,%7}, {%8,%9}, {%0,%1,%2,%3};"
    : "+f"(c[0]), "+f"(c[1]), "+f"(c[2]), "+f"(c[3])
    : "r"(a[0]), "r"(a[1]), "r"(a[2]), "r"(a[3]), "r"(b[0]), "r"(b[1]));
}

__device__ __forceinline__ void ldm_x4(uint32_t* r, uint32_t addr) {
  asm volatile("ldmatrix.sync.aligned.m8n8.x4.shared.b16 {%0,%1,%2,%3}, [%4];"
    : "=r"(r[0]), "=r"(r[1]), "=r"(r[2]), "=r"(r[3]) : "r"(addr));
}

// ---------------- fused: P = enc @ [aw2g|aw2c]; scores += tanh(q+P)*av ----------------
// block tile 128(M) x 128(N); 8 warps 4x2; warp tile 32x64. Never writes P.
__global__ void __launch_bounds__(256, 2) mma_attn_scores_kernel(
    const float* __restrict__ avg, const float* __restrict__ avc) {
  __shared__ uint32_t sAh[128*20];
  __shared__ uint32_t sAl[128*20];
  __shared__ uint32_t sBh[128*20];
  __shared__ uint32_t sBl[128*20];
  __shared__ float s_av[128];
  __shared__ float s_q[2][128];

  int tid = threadIdx.x;
  int bm = blockIdx.x * 128;     // 75
  int bn = blockIdx.y * 128;     // 8
  int wid = tid >> 5, lane = tid & 31;
  int wm = wid >> 1, wn = wid & 1;
  int g = lane >> 2, t4 = lane & 3;

  int b_lo = bm / 600;
  int b_hi = (bm + 127) / 600;
  if (tid < 128) {
    const float* av = (bn < 512) ? avg : avc;
    s_av[tid] = av[(bn & 511) + tid];
    s_q[0][tid] = g_q[b_lo*1024 + bn + tid];
    s_q[1][tid] = g_q[b_hi*1024 + bn + tid];
  }

  // ldmatrix byte addresses
  uint32_t baseAh = (uint32_t)__cvta_generic_to_shared(sAh);
  uint32_t baseAl = (uint32_t)__cvta_generic_to_shared(sAl);
  uint32_t baseBh = (uint32_t)__cvta_generic_to_shared(sBh);
  uint32_t baseBl = (uint32_t)__cvta_generic_to_shared(sBl);
  // A: 16 rows per mt tile; lane&15 -> row, lane>>4 -> k-half (4 u32)
  uint32_t aoff = ((uint32_t)((wm*32 + (lane & 15))*20 + (lane >> 4)*4)) * 4;
  uint32_t aAh0 = baseAh + aoff, aAl0 = baseAl + aoff;       // mt=0; mt=1 adds 16*20*4=1280
  // B: tile pair base; lane&7 + ((lane>>4)<<3) -> n row, (lane>>3)&1 -> k-half
  uint32_t boff = ((uint32_t)((wn*64 + (lane & 7) + ((lane >> 4) << 3))*20 + ((lane >> 3) & 1)*4)) * 4;
  uint32_t bBh0 = baseBh + boff, bBl0 = baseBl + boff;       // ntp adds ntp*16*20*4=1280

  float acc[2][8][4];
  #pragma unroll
  for (int mt=0;mt<2;mt++)
    #pragma unroll
    for (int nt=0;nt<8;nt++)
      #pragma unroll
      for (int r=0;r<4;r++) acc[mt][nt][r]=0.f;

  for (int kc=0; kc<512; kc+=32) {
    #pragma unroll
    for (int i=0;i<8;i++) {
      int e = tid + i*256;            // 0..2047
      int row = e >> 4, kw = e & 15;
      size_t ga = (size_t)(bm+row)*256 + (kc>>1) + kw;
      size_t gb = (size_t)(bn+row)*256 + (kc>>1) + kw;
      int ss = row*20 + kw;
      sAh[ss] = g_A2h[ga];
      sAl[ss] = g_A2l[ga];
      sBh[ss] = g_Wth[gb];
      sBl[ss] = g_Wtl[gb];
    }
    __syncthreads();

    #pragma unroll
    for (int ks=0; ks<2; ks++) {
      uint32_t kb = ks*32;   // bytes (8 u32)
      uint32_t ah[2][4], al[2][4];
      ldm_x4(ah[0], aAh0 + kb);
      ldm_x4(ah[1], aAh0 + 1280 + kb);
      ldm_x4(al[0], aAl0 + kb);
      ldm_x4(al[1], aAl0 + 1280 + kb);
      #pragma unroll
      for (int ntp=0; ntp<4; ntp++) {
        uint32_t bh4[4], bl4[4];
        ldm_x4(bh4, bBh0 + (uint32_t)ntp*1280 + kb);
        ldm_x4(bl4, bBl0 + (uint32_t)ntp*1280 + kb);
        int n0 = ntp*2, n1 = ntp*2+1;
        #pragma unroll
        for (int mt=0;mt<2;mt++) {
          mma16816(acc[mt][n0], ah[mt], bh4+0);
          mma16816(acc[mt][n0], ah[mt], bl4+0);
          mma16816(acc[mt][n0], al[mt], bh4+0);
          mma16816(acc[mt][n1], ah[mt], bh4+2);
          mma16816(acc[mt][n1], ah[mt], bl4+2);
          mma16816(acc[mt][n1], al[mt], bh4+2);
        }
      }
    }
    __syncthreads();
  }

  // fused scores epilogue: per row partial sum of tanh(q+p)*av, quad-reduce, atomicAdd
  float* dst = (bn < 512) ? g_sg : g_sc;
  #pragma unroll
  for (int mt=0;mt<2;mt++) {
    #pragma unroll
    for (int rh=0; rh<2; rh++) {
      int row = bm + wm*32 + mt*16 + g + rh*8;
      int b = row / 600;
      int qs = (b == b_lo) ? 0 : 1;
      float s = 0.f;
      #pragma unroll
      for (int nt=0; nt<8; nt++) {
        int cl = wn*64 + nt*8 + t4*2;
        s += tanhf(s_q[qs][cl]   + acc[mt][nt][rh*2+0]) * s_av[cl];
        s += tanhf(s_q[qs][cl+1] + acc[mt][nt][rh*2+1]) * s_av[cl+1];
      }
      s += __shfl_xor_sync(0xffffffffu, s, 1);
      s += __shfl_xor_sync(0xffffffffu, s, 2);
      if (t4 == 0) atomicAdd(&dst[row], s);
    }
  }
}

// ---------------- small-M GEMM, K-split + atomic accumulate ----------------
struct GArgs {
  const float* A0; const float* A1;
  const float* W0; const float* W1;
  const int* xidx; const float* emb;
  float* C;
  int K; int N;
};

enum { V_Z1=0, V_Z2=1, V_Q=2, V_HA=3 };

template<int VAR>
__device__ __forceinline__ float loadA(const GArgs& g, int b, int k) {
  if (VAR==V_Z1) {
    if (k < 300) return g.emb[(size_t)g.xidx[b]*300 + k];
    if (k < 812) return g.A0[b*512 + (k-300)];
    return g.A1[b*512 + (k-812)];
  }
  if (VAR==V_Z2 || VAR==V_HA) {
    if (k < 512) return g.A0[b*512+k];
    return g.A1[b*512 + (k-512)];
  }
  return g.A0[b*512+k]; // V_Q
}

template<int VAR>
__device__ __forceinline__ float loadW(const GArgs& g, int k, int c) {
  if (VAR==V_Z1) return (k<812) ? g.W0[(size_t)k*2048+c] : g.W1[(size_t)(k-812)*2048+c];
  if (VAR==V_Z2) return (k<512) ? g.W0[(size_t)k*2048+c] : g.W1[(size_t)(k-512)*2048+c];
  if (VAR==V_Q)  return (c<512) ? g.W0[(size_t)k*512+c]  : g.W1[(size_t)k*512+(c-512)];
  return g.W0[(size_t)k*512+c]; // V_HA
}

template<int VAR>
__global__ void gemm16_atomic(GArgs g) {
  __shared__ __align__(16) float As[64][16];
  int tid = threadIdx.x;                 // 128
  int col = blockIdx.x*128 + tid;
  int k0  = blockIdx.y*64;

  #pragma unroll
  for (int i=0;i<8;i++) {
    int e = tid + i*128;
    int kl = e >> 4, b = e & 15;
    int k = k0 + kl;
    As[kl][b] = (k < g.K) ? loadA<VAR>(g, b, k) : 0.f;
  }
  __syncthreads();

  float acc[16];
  #pragma unroll
  for (int b=0;b<16;b++) acc[b]=0.f;

  #pragma unroll 4
  for (int kl=0; kl<64; kl++) {
    int k = k0 + kl;
    float w = (k < g.K) ? loadW<VAR>(g, k, col) : 0.f;
    const float4* ap = (const float4*)&As[kl][0];
    float4 v0 = ap[0], v1 = ap[1], v2 = ap[2], v3 = ap[3];
    acc[0]  = fmaf(v0.x,w,acc[0]);  acc[1]  = fmaf(v0.y,w,acc[1]);
    acc[2]  = fmaf(v0.z,w,acc[2]);  acc[3]  = fmaf(v0.w,w,acc[3]);
    acc[4]  = fmaf(v1.x,w,acc[4]);  acc[5]  = fmaf(v1.y,w,acc[5]);
    acc[6]  = fmaf(v1.z,w,acc[6]);  acc[7]  = fmaf(v1.w,w,acc[7]);
    acc[8]  = fmaf(v2.x,w,acc[8]);  acc[9]  = fmaf(v2.y,w,acc[9]);
    acc[10] = fmaf(v2.z,w,acc[10]); acc[11] = fmaf(v2.w,w,acc[11]);
    acc[12] = fmaf(v3.x,w,acc[12]); acc[13] = fmaf(v3.y,w,acc[13]);
    acc[14] = fmaf(v3.z,w,acc[14]); acc[15] = fmaf(v3.w,w,acc[15]);
  }
  #pragma unroll
  for (int b=0;b<16;b++)
    atomicAdd(&g.C[(size_t)b*g.N + col], acc[b]);
}

// ---------------- logits: g_logits += ha @ Wg, K-split 4x128 ----------------
__global__ void gemm16_logits_split(const float* __restrict__ A, const float* __restrict__ W) {
  __shared__ __align__(16) float As[128][16];
  int tid = threadIdx.x;                 // 128
  int col = blockIdx.x*128 + tid;
  int k0  = blockIdx.y*128;
  #pragma unroll
  for (int i=0;i<16;i++) {
    int e = tid + i*128;
    int kl = e >> 4, b = e & 15;
    As[kl][b] = A[b*512 + k0 + kl];
  }
  __syncthreads();
  if (col >= VV) return;
  float acc[16];
  #pragma unroll
  for (int b=0;b<16;b++) acc[b]=0.f;
  #pragma unroll 8
  for (int kl=0; kl<128; kl++) {
    float w = W[(size_t)(k0+kl)*VV + col];
    const float4* ap = (const float4*)&As[kl][0];
    float4 v0 = ap[0], v1 = ap[1], v2 = ap[2], v3 = ap[3];
    acc[0]  = fmaf(v0.x,w,acc[0]);  acc[1]  = fmaf(v0.y,w,acc[1]);
    acc[2]  = fmaf(v0.z,w,acc[2]);  acc[3]  = fmaf(v0.w,w,acc[3]);
    acc[4]  = fmaf(v1.x,w,acc[4]);  acc[5]  = fmaf(v1.y,w,acc[5]);
    acc[6]  = fmaf(v1.z,w,acc[6]);  acc[7]  = fmaf(v1.w,w,acc[7]);
    acc[8]  = fmaf(v2.x,w,acc[8]);  acc[9]  = fmaf(v2.y,w,acc[9]);
    acc[10] = fmaf(v2.z,w,acc[10]); acc[11] = fmaf(v2.w,w,acc[11]);
    acc[12] = fmaf(v3.x,w,acc[12]); acc[13] = fmaf(v3.y,w,acc[13]);
    acc[14] = fmaf(v3.z,w,acc[14]); acc[15] = fmaf(v3.w,w,acc[15]);
  }
  #pragma unroll
  for (int b=0;b<16;b++)
    atomicAdd(&g_logits[(size_t)b*VV + col], acc[b]);
}

// ---------------- LSTM pointwise ----------------
__global__ void lstm_pw_kernel(const float* __restrict__ z, const float* __restrict__ cin,
                               float* __restrict__ hout, float* __restrict__ cout) {
  int idx = blockIdx.x*blockDim.x + threadIdx.x;
  if (idx >= BB*HH) return;
  int b = idx >> 9, j = idx & 511;
  const float* zb = z + b*2048;
  float iv = sigf(zb[j]);
  float fv = sigf(zb[512+j]);
  float gv = tanhf(zb[1024+j]);
  float ov = sigf(zb[1536+j]);
  float c = fv*cin[idx] + iv*gv;
  hout[idx] = ov*tanhf(c);
  cout[idx] = c;
}

// ---------------- softmax over T (both heads) ----------------
__global__ void softmax_kernel() {
  int b = blockIdx.x, tid = threadIdx.x;   // 256
  __shared__ float ag[TT], ac[TT];
  __shared__ float rbuf[256];
  for (int t=tid;t<TT;t+=256){ ag[t]=g_sg[b*TT+t]; ac[t]=g_sc[b*TT+t]; }
  __syncthreads();
  for (int pass=0; pass<2; pass++) {
    float* arr = pass ? ac : ag;
    float mx = -1e30f;
    for (int t=tid;t<TT;t+=256) mx = fmaxf(mx, arr[t]);
    rbuf[tid]=mx; __syncthreads();
    for (int s=128;s>0;s>>=1){ if (tid<s) rbuf[tid]=fmaxf(rbuf[tid],rbuf[tid+s]); __syncthreads(); }
    mx = rbuf[0]; __syncthreads();
    float ls=0.f;
    for (int t=tid;t<TT;t+=256){ float e=expf(arr[t]-mx); arr[t]=e; ls+=e; }
    rbuf[tid]=ls; __syncthreads();
    for (int s=128;s>0;s>>=1){ if (tid<s) rbuf[tid]+=rbuf[tid+s]; __syncthreads(); }
    float inv = 1.0f/rbuf[0]; __syncthreads();
    for (int t=tid;t<TT;t+=256) arr[t]*=inv;
    __syncthreads();
  }
  for (int t=tid;t<TT;t+=256){ g_aligng[b*TT+t]=ag[t]; g_alignc[b*TT+t]=ac[t]; }
}

// ---------------- context = align_g @ enc_outs, T-sliced + atomic ----------------
__global__ void ctx_kernel(const float* __restrict__ enc) {
  int s = blockIdx.x;            // 0..9
  int b = blockIdx.y;
  int tid = threadIdx.x;         // 512
  __shared__ float ag[60];
  if (tid < 60) ag[tid] = g_aligng[b*TT + s*60 + tid];
  __syncthreads();
  const float* eb = enc + (size_t)b*TT*HH + (size_t)(s*60)*HH + tid;
  float a0=0.f,a1=0.f,a2=0.f,a3=0.f,a4=0.f,a5=0.f;
  #pragma unroll 2
  for (int t=0;t<60;t+=6){
    a0 += ag[t]  *eb[(size_t)(t  )*HH];
    a1 += ag[t+1]*eb[(size_t)(t+1)*HH];
    a2 += ag[t+2]*eb[(size_t)(t+2)*HH];
    a3 += ag[t+3]*eb[(size_t)(t+3)*HH];
    a4 += ag[t+4]*eb[(size_t)(t+4)*HH];
    a5 += ag[t+5]*eb[(size_t)(t+5)*HH];
  }
  atomicAdd(&g_ctx[b*HH+tid], (a0+a1)+(a2+a3)+(a4+a5));
}

// ---------------- hidden_att finalize: tanh + switch ----------------
__global__ void ha_finalize_kernel(float* __restrict__ out_hidden,
                                   const float* __restrict__ Wf, const float* __restrict__ bf) {
  int b = blockIdx.x, tid = threadIdx.x;   // 512
  __shared__ float rb[512];
  float t = tanhf(g_ha[b*HH+tid]);
  out_hidden[b*HH+tid] = t;
  rb[tid] = t*Wf[tid];
  __syncthreads();
  for (int s=256;s>0;s>>=1){ if (tid<s) rb[tid]+=rb[tid+s]; __syncthreads(); }
  if (tid==0) g_switch[b] = sigf(rb[0]+bf[0]);
}

// ---------------- vocab softmax reductions, two-stage ----------------
__global__ void vred1_kernel() {
  int s = blockIdx.x, b = blockIdx.y;      // 10 x 16
  int tid = threadIdx.x;                   // 256
  __shared__ float rb[256];
  const float* lb = g_logits + (size_t)b*VV + s*2000;
  float mx = -1e30f;
  for (int i=tid;i<2000;i+=256) mx = fmaxf(mx, lb[i]);
  rb[tid]=mx; __syncthreads();
  for (int st=128;st>0;st>>=1){ if (tid<st) rb[tid]=fmaxf(rb[tid],rb[tid+st]); __syncthreads(); }
  mx = rb[0]; __syncthreads();
  float sm=0.f;
  for (int i=tid;i<2000;i+=256) sm += expf(lb[i]-mx);
  rb[tid]=sm; __syncthreads();
  for (int st=128;st>0;st>>=1){ if (tid<st) rb[tid]+=rb[tid+st]; __syncthreads(); }
  if (tid==0){ g_pm[b*10+s]=mx; g_ps[b*10+s]=rb[0]; }
}

__global__ void vred2_kernel() {
  int b = blockIdx.x, tid = threadIdx.x;   // 32
  float m = (tid<10) ? g_pm[b*10+tid] : -1e30f;
  #pragma unroll
  for (int o=16;o>0;o>>=1) m = fmaxf(m, __shfl_xor_sync(0xffffffffu, m, o));
  float s = (tid<10) ? g_ps[b*10+tid]*expf(g_pm[b*10+tid]-m) : 0.f;
  #pragma unroll
  for (int o=16;o>0;o>>=1) s += __shfl_xor_sync(0xffffffffu, s, o);
  if (tid==0){ g_vred[b*2]=m; g_vred[b*2+1]=s; }
}

// ---------------- final: copy_prob stream + mix ----------------
__global__ void final_kernel(const float* __restrict__ enc_ins, float* __restrict__ result) {
  int b = blockIdx.y, tid = threadIdx.x;   // 512
  int v = blockIdx.x*512 + tid;
  __shared__ float ac[TT];
  for (int t=tid;t<TT;t+=512) ac[t]=g_alignc[b*TT+t];
  __syncthreads();
  if (v >= VV) return;
  const float* eb = enc_ins + (size_t)b*TT*VV + v;
  float a0=0.f,a1=0.f,a2=0.f,a3=0.f,a4=0.f,a5=0.f,a6=0.f,a7=0.f;
  for (int t=0;t<TT;t+=8){
    a0 += ac[t]  * eb[(size_t)(t  )*VV];
    a1 += ac[t+1]* eb[(size_t)(t+1)*VV];
    a2 += ac[t+2]* eb[(size_t)(t+2)*VV];
    a3 += ac[t+3]* eb[(size_t)(t+3)*VV];
    a4 += ac[t+4]* eb[(size_t)(t+4)*VV];
    a5 += ac[t+5]* eb[(size_t)(t+5)*VV];
    a6 += ac[t+6]* eb[(size_t)(t+6)*VV];
    a7 += ac[t+7]* eb[(size_t)(t+7)*VV];
  }
  float copy = ((a0+a1)+(a2+a3))+((a4+a5)+(a6+a7));
  float sw = g_switch[b];
  float mx = g_vred[b*2], sm = g_vred[b*2+1];
  float gen = expf(g_logits[(size_t)b*VV+v]-mx)/sm;
  result[(size_t)b*VV+v] = gen*(1.0f-sw) + copy*sw;
}

// ---------------- launch ----------------
extern "C" void kernel_launch(void* const* d_in, const int* in_sizes, int n_in,
                              void* d_out, int out_size) {
  const int*   x        = (const int*)  d_in[0];
  const float* lha      = (const float*)d_in[1];
  const float* h1       = (const float*)d_in[2];
  const float* c1       = (const float*)d_in[3];
  const float* h2       = (const float*)d_in[4];
  const float* c2       = (const float*)d_in[5];
  const float* enc_outs = (const float*)d_in[6];
  const float* enc_ins  = (const float*)d_in[7];
  const float* emb      = (const float*)d_in[8];
  const float* k1       = (const float*)d_in[9];
  const float* r1       = (const float*)d_in[10];
  const float* b1       = (const float*)d_in[11];
  const float* k2       = (const float*)d_in[12];
  const float* r2       = (const float*)d_in[13];
  const float* b2       = (const float*)d_in[14];
  const float* Wh       = (const float*)d_in[15];
  const float* bh       = (const float*)d_in[16];
  const float* Wg       = (const float*)d_in[17];
  const float* bg       = (const float*)d_in[18];
  const float* Wf       = (const float*)d_in[19];
  const float* bf       = (const float*)d_in[20];
  const float* aw1g     = (const float*)d_in[21];
  const float* aw2g     = (const float*)d_in[22];
  const float* avg      = (const float*)d_in[23];
  const float* aw1c     = (const float*)d_in[24];
  const float* aw2c     = (const float*)d_in[25];
  const float* avc      = (const float*)d_in[26];

  float* out = (float*)d_out;
  float* out_result = out;                       // 16*20000
  float* out_hidden = out + BB*VV;
  float* out_h1n    = out_hidden + BB*HH;
  float* out_c1n    = out_h1n + BB*HH;
  float* out_h2n    = out_c1n + BB*HH;
  float* out_c2n    = out_h2n + BB*HH;

  float *p_z1, *p_z2, *p_q, *p_ctx, *p_ha;
  cudaGetSymbolAddress((void**)&p_z1, g_z1);
  cudaGetSymbolAddress((void**)&p_z2, g_z2);
  cudaGetSymbolAddress((void**)&p_q, g_q);
  cudaGetSymbolAddress((void**)&p_ctx, g_ctx);
  cudaGetSymbolAddress((void**)&p_ha, g_ha);

  init_kernel<<<(INIT_TOTAL+255)/256, 256>>>(b1, b2, bh, bg);

  // convert inputs for tensor-core GEMM
  convA_kernel<<<(BT*512/4 + 255)/256, 256>>>(enc_outs);
  convW_kernel<<<dim3(16,32), 256>>>(aw2g, aw2c);

  // LSTM 1
  GArgs az1; az1.A0=lha; az1.A1=h1; az1.W0=k1; az1.W1=r1;
  az1.xidx=x; az1.emb=emb; az1.C=p_z1; az1.K=1324; az1.N=2048;
  gemm16_atomic<V_Z1><<<dim3(16,21),128>>>(az1);
  lstm_pw_kernel<<<32,256>>>(p_z1, c1, out_h1n, out_c1n);

  // LSTM 2
  GArgs az2; az2.A0=out_h1n; az2.A1=h2; az2.W0=k2; az2.W1=r2;
  az2.xidx=nullptr; az2.emb=nullptr; az2.C=p_z2; az2.K=1024; az2.N=2048;
  gemm16_atomic<V_Z2><<<dim3(16,16),128>>>(az2);
  lstm_pw_kernel<<<32,256>>>(p_z2, c2, out_h2n, out_c2n);

  // queries (both heads)
  GArgs aq; aq.A0=out_h2n; aq.A1=nullptr; aq.W0=aw1g; aq.W1=aw1c;
  aq.xidx=nullptr; aq.emb=nullptr; aq.C=p_q; aq.K=512; aq.N=1024;
  gemm16_atomic<V_Q><<<dim3(8,8),128>>>(aq);

  // fused big GEMM + scores (needs q; never materializes P)
  mma_attn_scores_kernel<<<dim3(75,8), 256>>>(avg, avc);

  softmax_kernel<<<BB,256>>>();
  ctx_kernel<<<dim3(10,BB),512>>>(enc_outs);

  GArgs aha; aha.A0=p_ctx; aha.A1=out_h2n; aha.W0=Wh; aha.W1=nullptr;
  aha.xidx=nullptr; aha.emb=nullptr; aha.C=p_ha; aha.K=1024; aha.N=512;
  gemm16_atomic<V_HA><<<dim3(4,16),128>>>(aha);
  ha_finalize_kernel<<<BB,512>>>(out_hidden, Wf, bf);

  gemm16_logits_split<<<dim3((VV+127)/128, 4),128>>>(out_hidden, Wg);
  vred1_kernel<<<dim3(10,BB),256>>>();
  vred2_kernel<<<BB,32>>>();

  final_kernel<<<dim3((VV+511)/512, BB), 512>>>(enc_ins, out_result);
}